// round 5
// baseline (speedup 1.0000x reference)
#include <cuda_runtime.h>

#define BATCH 256
#define VOCAB 128000
#define RANK  64
#define ALPHA 0.4f
#define EPSF  1.1920928955078125e-07f   // np.finfo(float32).eps

// ---------------- scratch (no allocations allowed) ----------------
__device__ float        g_T[BATCH * RANK];   // T = L @ W  [256,64]
__device__ unsigned int g_maxL;              // float bits of max|L|  (abs -> monotonic as uint)
__device__ unsigned int g_maxLp;             // float bits of max|Lp_raw|

// ---------------- K0: init ----------------
__global__ void k_init() {
    int i = blockIdx.x * blockDim.x + threadIdx.x;
    if (i < BATCH * RANK) g_T[i] = 0.0f;
    if (i == 0) { g_maxL = 0u; g_maxLp = 0u; }
}

// ---------------- K1: partial T = L@W over a k-chunk, fused max|L| ----------------
// grid = VOCAB/KC blocks, 256 threads. Per-thread tile: 8 batch x 8 rank.
#define KC 512
#define KB 32
#define LS_STRIDE 33    // Ls[b][kk], pad 1 -> conflict-free
#define WS_STRIDE 68    // Ws[kk][r], pad 4, f4-aligned

__global__ __launch_bounds__(256) void k_gemm1(const float* __restrict__ L,
                                               const float* __restrict__ W) {
    __shared__ float Ls[BATCH * LS_STRIDE];   // 33792 B
    __shared__ float Ws[KB * WS_STRIDE];      //  8704 B
    __shared__ float wred[8];

    const int tid = threadIdx.x;
    const int tx  = tid & 7;    // rank group (8 ranks each)
    const int ty  = tid >> 3;   // batch group (8 rows each)
    const int k0blk = blockIdx.x * KC;

    float acc[8][8];
#pragma unroll
    for (int i = 0; i < 8; i++)
#pragma unroll
        for (int j = 0; j < 8; j++) acc[i][j] = 0.0f;

    float maxl = 0.0f;

    for (int kt = 0; kt < KC; kt += KB) {
        const int k0 = k0blk + kt;
        __syncthreads();
        // load L chunk [256 b][32 k] -> Ls[b][kk]; fused abs-max
#pragma unroll
        for (int it = 0; it < 8; it++) {
            int idx = tid + it * 256;          // float4 index, 2048 total
            int b   = idx >> 3;                // 8 float4 per row
            int kq  = idx & 7;
            float4 v = *(const float4*)(L + (size_t)b * VOCAB + k0 + kq * 4);
            maxl = fmaxf(maxl, fmaxf(fmaxf(fabsf(v.x), fabsf(v.y)),
                                     fmaxf(fabsf(v.z), fabsf(v.w))));
            float* dst = &Ls[b * LS_STRIDE + kq * 4];
            dst[0] = v.x; dst[1] = v.y; dst[2] = v.z; dst[3] = v.w;
        }
        // load W chunk [32 k][64 r] -> Ws[kk][r]
#pragma unroll
        for (int it = 0; it < 2; it++) {
            int idx = tid + it * 256;          // float4 index, 512 total
            int kk  = idx >> 4;                // 16 float4 per row
            int rq  = idx & 15;
            float4 v = *(const float4*)(W + (size_t)(k0 + kk) * RANK + rq * 4);
            float* dst = &Ws[kk * WS_STRIDE + rq * 4];
            dst[0] = v.x; dst[1] = v.y; dst[2] = v.z; dst[3] = v.w;
        }
        __syncthreads();
#pragma unroll
        for (int kk = 0; kk < KB; kk++) {
            float4 w0 = *(const float4*)&Ws[kk * WS_STRIDE + tx * 8];
            float4 w1 = *(const float4*)&Ws[kk * WS_STRIDE + tx * 8 + 4];
            float wv[8] = {w0.x, w0.y, w0.z, w0.w, w1.x, w1.y, w1.z, w1.w};
#pragma unroll
            for (int i = 0; i < 8; i++) {
                float lv = Ls[(ty * 8 + i) * LS_STRIDE + kk];
#pragma unroll
                for (int j = 0; j < 8; j++)
                    acc[i][j] = fmaf(lv, wv[j], acc[i][j]);
            }
        }
    }

    // accumulate partial T
#pragma unroll
    for (int i = 0; i < 8; i++)
#pragma unroll
        for (int j = 0; j < 8; j++)
            atomicAdd(&g_T[(ty * 8 + i) * RANK + tx * 8 + j], acc[i][j]);

    // block-reduce max|L|
#pragma unroll
    for (int off = 16; off > 0; off >>= 1)
        maxl = fmaxf(maxl, __shfl_xor_sync(0xffffffffu, maxl, off));
    __syncthreads();
    if ((tid & 31) == 0) wred[tid >> 5] = maxl;
    __syncthreads();
    if (tid == 0) {
        float m = wred[0];
#pragma unroll
        for (int k = 1; k < 8; k++) m = fmaxf(m, wred[k]);
        atomicMax(&g_maxL, __float_as_uint(m));
    }
}

// ---------------- K2: Lp = T@W.T - L -> d_out, fused max|Lp| ----------------
// grid = (VOCAB/64, 2), 256 threads. Tile: 128 batch x 64 vocab; per-thread 8b x 4j.
#define JB 64
#define BT 128
#define WS2_STRIDE 68           // Ws[j][r], pad 4
#define SMEM2_BYTES ((BT * RANK + JB * WS2_STRIDE) * 4)   // 32768 + 17408 = 50176

__global__ __launch_bounds__(256) void k_gemm2(const float* __restrict__ L,
                                               const float* __restrict__ W,
                                               float* __restrict__ out) {
    extern __shared__ float sm[];
    float* Ts = sm;                 // [128][64]
    float* Ws = sm + BT * RANK;     // [64][68]

    const int tid = threadIdx.x;
    const int tx  = tid & 15;      // j group (4 each)
    const int ty  = tid >> 4;      // b group (8 each)
    const int j0  = blockIdx.x * JB;
    const int b0  = blockIdx.y * BT;

    // load T slice [128][64] (row-major copy)
    {
        const float4* src = (const float4*)(g_T) + b0 * (RANK / 4);
        float4* dst = (float4*)Ts;
#pragma unroll
        for (int it = 0; it < 8; it++) {
            int idx = tid + it * 256;   // 2048 float4
            dst[idx] = src[idx];
        }
    }
    // load W tile [64 j][64 r] -> Ws[j][r]
#pragma unroll
    for (int it = 0; it < 4; it++) {
        int idx = tid + it * 256;       // 1024 float4
        int jj  = idx >> 4;
        int rq  = idx & 15;
        float4 v = *(const float4*)(W + (size_t)(j0 + jj) * RANK + rq * 4);
        float* dst = &Ws[jj * WS2_STRIDE + rq * 4];
        dst[0] = v.x; dst[1] = v.y; dst[2] = v.z; dst[3] = v.w;
    }
    __syncthreads();

    float acc[8][4];
#pragma unroll
    for (int i = 0; i < 8; i++)
#pragma unroll
        for (int jj = 0; jj < 4; jj++) acc[i][jj] = 0.0f;

#pragma unroll
    for (int r4 = 0; r4 < RANK / 4; r4++) {
        float4 wq[4];
#pragma unroll
        for (int jj = 0; jj < 4; jj++)
            wq[jj] = *(const float4*)&Ws[(tx * 4 + jj) * WS2_STRIDE + r4 * 4];
#pragma unroll
        for (int i = 0; i < 8; i++) {
            float4 tq = *(const float4*)&Ts[(ty * 8 + i) * RANK + r4 * 4];
#pragma unroll
            for (int jj = 0; jj < 4; jj++) {
                acc[i][jj] = fmaf(tq.x, wq[jj].x, acc[i][jj]);
                acc[i][jj] = fmaf(tq.y, wq[jj].y, acc[i][jj]);
                acc[i][jj] = fmaf(tq.z, wq[jj].z, acc[i][jj]);
                acc[i][jj] = fmaf(tq.w, wq[jj].w, acc[i][jj]);
            }
        }
    }

    // epilogue: Lp = acc - L, write raw Lp, track max|Lp|
    float maxlp = 0.0f;
    const int jcol = j0 + tx * 4;
#pragma unroll
    for (int i = 0; i < 8; i++) {
        const size_t b = (size_t)(b0 + ty * 8 + i);
        float4 lv = *(const float4*)(L + b * VOCAB + jcol);
        float4 o;
        o.x = acc[i][0] - lv.x;
        o.y = acc[i][1] - lv.y;
        o.z = acc[i][2] - lv.z;
        o.w = acc[i][3] - lv.w;
        maxlp = fmaxf(maxlp, fmaxf(fmaxf(fabsf(o.x), fabsf(o.y)),
                                   fmaxf(fabsf(o.z), fabsf(o.w))));
        *(float4*)(out + b * VOCAB + jcol) = o;
    }

#pragma unroll
    for (int off = 16; off > 0; off >>= 1)
        maxlp = fmaxf(maxlp, __shfl_xor_sync(0xffffffffu, maxlp, off));
    __syncthreads();                 // done reading Ts -> reuse for reduction
    if ((tid & 31) == 0) Ts[tid >> 5] = maxlp;
    __syncthreads();
    if (tid == 0) {
        float m = Ts[0];
#pragma unroll
        for (int k = 1; k < 8; k++) m = fmaxf(m, Ts[k]);
        atomicMax(&g_maxLp, __float_as_uint(m));
    }
}

// ---------------- K3: out = (1-a)*scale*Lp + a*L ----------------
__global__ void k_final(const float* __restrict__ L, float* __restrict__ out) {
    const float maxl  = __uint_as_float(g_maxL);
    const float maxlp = __uint_as_float(g_maxLp);
    const float scale = maxl / fmaxf(maxlp, EPSF);
    const float c2 = (1.0f - ALPHA) * scale;

    const int n4 = BATCH * VOCAB / 4;
    float4* o4 = (float4*)out;
    const float4* l4 = (const float4*)L;
    for (int i = blockIdx.x * blockDim.x + threadIdx.x; i < n4;
         i += gridDim.x * blockDim.x) {
        float4 o = o4[i];
        float4 l = l4[i];
        o.x = fmaf(c2, o.x, ALPHA * l.x);
        o.y = fmaf(c2, o.y, ALPHA * l.y);
        o.z = fmaf(c2, o.z, ALPHA * l.z);
        o.w = fmaf(c2, o.w, ALPHA * l.w);
        o4[i] = o;
    }
}

// ---------------- launch ----------------
extern "C" void kernel_launch(void* const* d_in, const int* in_sizes, int n_in,
                              void* d_out, int out_size) {
    // identify inputs by element count (token_ids unused)
    const float* L = nullptr;
    const float* W = nullptr;
    for (int i = 0; i < n_in; i++) {
        if (in_sizes[i] == BATCH * VOCAB)     L = (const float*)d_in[i];
        else if (in_sizes[i] == VOCAB * RANK) W = (const float*)d_in[i];
    }
    // fallback: positional per reference signature (token_ids, logits, W)
    if (!L && n_in >= 2) L = (const float*)d_in[1];
    if (!W && n_in >= 3) W = (const float*)d_in[2];
    float* out = (float*)d_out;

    k_init<<<(BATCH * RANK + 255) / 256, 256>>>();
    k_gemm1<<<VOCAB / KC, 256>>>(L, W);
    cudaFuncSetAttribute(k_gemm2, cudaFuncAttributeMaxDynamicSharedMemorySize,
                         SMEM2_BYTES);
    k_gemm2<<<dim3(VOCAB / JB, BATCH / BT), 256, SMEM2_BYTES>>>(L, W, out);
    k_final<<<4000, 256>>>(L, out);
}

// round 6
// speedup vs baseline: 1.9313x; 1.9313x over previous
#include <cuda_runtime.h>

#define BATCH 256
#define VOCAB 128000
#define RANK  64
#define ALPHA 0.4f
#define EPSF  1.1920928955078125e-07f   // np.finfo(float32).eps

// ---------------- scratch (no allocations allowed) ----------------
__device__ float        g_T[BATCH * RANK];   // T = L @ W  [256,64]
__device__ unsigned int g_maxL;              // float bits of max|L|
__device__ unsigned int g_maxLp;             // float bits of max|Lp_raw|

// ---------------- f32x2 / shared-memory PTX helpers ----------------
typedef unsigned long long u64;

__device__ __forceinline__ unsigned smem_u32(const void* p) {
    unsigned a;
    asm("{ .reg .u64 t; cvta.to.shared.u64 t, %1; cvt.u32.u64 %0, t; }"
        : "=r"(a) : "l"(p));
    return a;
}
__device__ __forceinline__ u64 lds_b64(unsigned a) {
    u64 v; asm volatile("ld.shared.b64 %0, [%1];" : "=l"(v) : "r"(a)); return v;
}
__device__ __forceinline__ void lds_v2b64(unsigned a, u64& v0, u64& v1) {
    asm volatile("ld.shared.v2.b64 {%0,%1}, [%2];" : "=l"(v0), "=l"(v1) : "r"(a));
}
__device__ __forceinline__ void sts_b64(unsigned a, u64 v) {
    asm volatile("st.shared.b64 [%0], %1;" :: "r"(a), "l"(v));
}
__device__ __forceinline__ u64 fma2(u64 a, u64 b, u64 c) {
    u64 d; asm("fma.rn.f32x2 %0, %1, %2, %3;" : "=l"(d) : "l"(a), "l"(b), "l"(c));
    return d;
}
__device__ __forceinline__ u64 pack2(float x, float y) {
    u64 v; asm("mov.b64 %0, {%1,%2};" : "=l"(v) : "f"(x), "f"(y)); return v;
}
__device__ __forceinline__ void unpack2(u64 v, float& x, float& y) {
    asm("mov.b64 {%0,%1}, %2;" : "=f"(x), "=f"(y) : "l"(v));
}

// ---------------- K0: init ----------------
__global__ void k_init() {
    int i = blockIdx.x * blockDim.x + threadIdx.x;
    if (i < BATCH * RANK) g_T[i] = 0.0f;
    if (i == 0) { g_maxL = 0u; g_maxLp = 0u; }
}

// ---------------- K1: T = L@W (k-chunked, FFMA2, fused max|L|) ----------------
// grid = VOCAB/KC, 256 threads. Thread tile: 8 batch (4 pairs) x 8 rank.
#define KC 512
#define KB 32
#define LST 258                 // Ls_t[kk][b] stride (even -> 8B-aligned b-pairs)
#define WDS 160                 // Wd[kk][...] dup layout: r -> (r>>3)*20 + (r&7)*2
#define G1_FLOATS (KB * LST + KB * WDS)          // 8256 + 5120 = 13376
#define G1_SMEM   (G1_FLOATS * 4)                // 53504 B

__global__ __launch_bounds__(256, 2) void k_gemm1(const float* __restrict__ L,
                                                  const float* __restrict__ W) {
    extern __shared__ float sm1[];
    float* Ls_t = sm1;                    // [KB][LST]
    float* Wd   = sm1 + KB * LST;         // [KB][WDS] duplicated pairs
    __shared__ float wred[8];

    const unsigned ls_base = smem_u32(Ls_t);
    const unsigned wd_base = smem_u32(Wd);

    const int tid = threadIdx.x;
    const int tx  = tid & 7;    // rank group (8 ranks)
    const int ty  = tid >> 3;   // batch group (8 rows = 4 pairs)
    const int k0blk = blockIdx.x * KC;

    u64 acc[4][8];
#pragma unroll
    for (int ip = 0; ip < 4; ip++)
#pragma unroll
        for (int j = 0; j < 8; j++) acc[ip][j] = 0ull;

    float maxl = 0.0f;

    for (int kt = 0; kt < KC; kt += KB) {
        const int k0 = k0blk + kt;
        __syncthreads();
        // L chunk [256 b][32 k] -> transposed Ls_t[kk][b]; fused abs-max
#pragma unroll
        for (int it = 0; it < 8; it++) {
            int idx = tid + it * 256;          // float4 index, 2048 total
            int b   = idx >> 3;
            int kq  = idx & 7;
            float4 v = *(const float4*)(L + (size_t)b * VOCAB + k0 + kq * 4);
            maxl = fmaxf(maxl, fmaxf(fmaxf(fabsf(v.x), fabsf(v.y)),
                                     fmaxf(fabsf(v.z), fabsf(v.w))));
            Ls_t[(kq * 4 + 0) * LST + b] = v.x;
            Ls_t[(kq * 4 + 1) * LST + b] = v.y;
            Ls_t[(kq * 4 + 2) * LST + b] = v.z;
            Ls_t[(kq * 4 + 3) * LST + b] = v.w;
        }
        // W chunk [32 k][64 r] -> duplicated pairs Wd[kk][(r>>3)*20 + (r&7)*2]
#pragma unroll
        for (int it = 0; it < 2; it++) {
            int idx = tid + it * 256;          // float4 index, 512 total
            int kk  = idx >> 4;
            int rq  = idx & 15;
            float4 v = *(const float4*)(W + (size_t)(k0 + kk) * RANK + rq * 4);
            int r0 = rq * 4;
            unsigned base = wd_base + (kk * WDS) * 4;
            sts_b64(base + ((r0 >> 3) * 20 + ((r0 + 0) & 7) * 2) * 4, pack2(v.x, v.x));
            sts_b64(base + (((r0+1) >> 3) * 20 + ((r0 + 1) & 7) * 2) * 4, pack2(v.y, v.y));
            sts_b64(base + (((r0+2) >> 3) * 20 + ((r0 + 2) & 7) * 2) * 4, pack2(v.z, v.z));
            sts_b64(base + (((r0+3) >> 3) * 20 + ((r0 + 3) & 7) * 2) * 4, pack2(v.w, v.w));
        }
        __syncthreads();

#pragma unroll
        for (int kk = 0; kk < KB; kk++) {
            const unsigned la = ls_base + (kk * LST + ty * 8) * 4;
            u64 lvp[4];
#pragma unroll
            for (int ip = 0; ip < 4; ip++) lvp[ip] = lds_b64(la + ip * 8);

            const unsigned wa = wd_base + (kk * WDS + tx * 20) * 4;
            u64 wdp[8];
            lds_v2b64(wa +  0, wdp[0], wdp[1]);
            lds_v2b64(wa + 16, wdp[2], wdp[3]);
            lds_v2b64(wa + 32, wdp[4], wdp[5]);
            lds_v2b64(wa + 48, wdp[6], wdp[7]);

#pragma unroll
            for (int ip = 0; ip < 4; ip++)
#pragma unroll
                for (int j = 0; j < 8; j++)
                    acc[ip][j] = fma2(lvp[ip], wdp[j], acc[ip][j]);
        }
    }

    // accumulate partial T
#pragma unroll
    for (int ip = 0; ip < 4; ip++)
#pragma unroll
        for (int j = 0; j < 8; j++) {
            float lo, hi;
            unpack2(acc[ip][j], lo, hi);
            int b = ty * 8 + ip * 2;
            int r = tx * 8 + j;
            atomicAdd(&g_T[(b + 0) * RANK + r], lo);
            atomicAdd(&g_T[(b + 1) * RANK + r], hi);
        }

    // block-reduce max|L|
#pragma unroll
    for (int off = 16; off > 0; off >>= 1)
        maxl = fmaxf(maxl, __shfl_xor_sync(0xffffffffu, maxl, off));
    __syncthreads();
    if ((tid & 31) == 0) wred[tid >> 5] = maxl;
    __syncthreads();
    if (tid == 0) {
        float m = wred[0];
#pragma unroll
        for (int k = 1; k < 8; k++) m = fmaxf(m, wred[k]);
        atomicMax(&g_maxL, __float_as_uint(m));
    }
}

// ---------------- K2: Lp = T@W.T - L -> d_out (FFMA2 over rank pairs) ----------------
// grid = (VOCAB/64, 2), 256 threads. Tile 128 b x 64 j; thread: 8b x 4j (j strided by 16).
#define JB 64
#define BT 128
#define WS2 68                  // Ws[j][r] stride
#define SMEM2_BYTES ((BT * RANK + JB * WS2) * 4)   // 50176

__global__ __launch_bounds__(256, 2) void k_gemm2(const float* __restrict__ L,
                                                  const float* __restrict__ W,
                                                  float* __restrict__ out) {
    extern __shared__ float sm[];
    float* Ts = sm;                 // [128][64]
    float* Ws = sm + BT * RANK;     // [64][68]

    const unsigned ts_base = smem_u32(Ts);
    const unsigned ws_base = smem_u32(Ws);

    const int tid = threadIdx.x;
    const int tx  = tid & 15;      // j lane (cols j0 + jj*16 + tx)
    const int ty  = tid >> 4;      // b group (8 rows)
    const int j0  = blockIdx.x * JB;
    const int b0  = blockIdx.y * BT;

    // load T slice [128][64]
    {
        const float4* src = (const float4*)(g_T) + b0 * (RANK / 4);
        float4* dst = (float4*)Ts;
#pragma unroll
        for (int it = 0; it < 8; it++) dst[tid + it * 256] = src[tid + it * 256];
    }
    // load W tile [64 j][64 r] -> Ws[j][r]
#pragma unroll
    for (int it = 0; it < 4; it++) {
        int idx = tid + it * 256;       // 1024 float4
        int jj  = idx >> 4;
        int rq  = idx & 15;
        float4 v = *(const float4*)(W + (size_t)(j0 + jj) * RANK + rq * 4);
        float* dst = &Ws[jj * WS2 + rq * 4];
        dst[0] = v.x; dst[1] = v.y; dst[2] = v.z; dst[3] = v.w;
    }
    __syncthreads();

    u64 acc[8][4];                 // even/odd rank partial sums
#pragma unroll
    for (int i = 0; i < 8; i++)
#pragma unroll
        for (int jj = 0; jj < 4; jj++) acc[i][jj] = 0ull;

#pragma unroll
    for (int r4 = 0; r4 < RANK / 4; r4++) {
        u64 wp0[4], wp1[4];
#pragma unroll
        for (int jj = 0; jj < 4; jj++)
            lds_v2b64(ws_base + ((jj * 16 + tx) * WS2 + r4 * 4) * 4, wp0[jj], wp1[jj]);
#pragma unroll
        for (int i = 0; i < 8; i++) {
            u64 tp0, tp1;
            lds_v2b64(ts_base + ((ty * 8 + i) * RANK + r4 * 4) * 4, tp0, tp1);
#pragma unroll
            for (int jj = 0; jj < 4; jj++) {
                acc[i][jj] = fma2(tp0, wp0[jj], acc[i][jj]);
                acc[i][jj] = fma2(tp1, wp1[jj], acc[i][jj]);
            }
        }
    }

    // epilogue: Lp = (lo+hi) - L, write raw Lp, track max|Lp|
    float maxlp = 0.0f;
#pragma unroll
    for (int i = 0; i < 8; i++) {
        const size_t b = (size_t)(b0 + ty * 8 + i);
#pragma unroll
        for (int jj = 0; jj < 4; jj++) {
            float lo, hi;
            unpack2(acc[i][jj], lo, hi);
            int j = j0 + jj * 16 + tx;
            float o = (lo + hi) - L[b * VOCAB + j];
            maxlp = fmaxf(maxlp, fabsf(o));
            out[b * VOCAB + j] = o;
        }
    }

#pragma unroll
    for (int off = 16; off > 0; off >>= 1)
        maxlp = fmaxf(maxlp, __shfl_xor_sync(0xffffffffu, maxlp, off));
    __syncthreads();                 // done reading Ts -> reuse for reduction
    if ((tid & 31) == 0) Ts[tid >> 5] = maxlp;
    __syncthreads();
    if (tid == 0) {
        float m = Ts[0];
#pragma unroll
        for (int k = 1; k < 8; k++) m = fmaxf(m, Ts[k]);
        atomicMax(&g_maxLp, __float_as_uint(m));
    }
}

// ---------------- K3: out = (1-a)*scale*Lp + a*L ----------------
__global__ void k_final(const float* __restrict__ L, float* __restrict__ out) {
    const float maxl  = __uint_as_float(g_maxL);
    const float maxlp = __uint_as_float(g_maxLp);
    const float scale = maxl / fmaxf(maxlp, EPSF);
    const float c2 = (1.0f - ALPHA) * scale;

    const int n4 = BATCH * VOCAB / 4;
    float4* o4 = (float4*)out;
    const float4* l4 = (const float4*)L;
    for (int i = blockIdx.x * blockDim.x + threadIdx.x; i < n4;
         i += gridDim.x * blockDim.x) {
        float4 o = o4[i];
        float4 l = l4[i];
        o.x = fmaf(c2, o.x, ALPHA * l.x);
        o.y = fmaf(c2, o.y, ALPHA * l.y);
        o.z = fmaf(c2, o.z, ALPHA * l.z);
        o.w = fmaf(c2, o.w, ALPHA * l.w);
        o4[i] = o;
    }
}

// ---------------- launch ----------------
extern "C" void kernel_launch(void* const* d_in, const int* in_sizes, int n_in,
                              void* d_out, int out_size) {
    const float* L = nullptr;
    const float* W = nullptr;
    for (int i = 0; i < n_in; i++) {
        if (in_sizes[i] == BATCH * VOCAB)     L = (const float*)d_in[i];
        else if (in_sizes[i] == VOCAB * RANK) W = (const float*)d_in[i];
    }
    if (!L && n_in >= 2) L = (const float*)d_in[1];
    if (!W && n_in >= 3) W = (const float*)d_in[2];
    float* out = (float*)d_out;

    cudaFuncSetAttribute(k_gemm1, cudaFuncAttributeMaxDynamicSharedMemorySize,
                         G1_SMEM);
    cudaFuncSetAttribute(k_gemm2, cudaFuncAttributeMaxDynamicSharedMemorySize,
                         SMEM2_BYTES);

    k_init<<<(BATCH * RANK + 255) / 256, 256>>>();
    k_gemm1<<<VOCAB / KC, 256, G1_SMEM>>>(L, W);
    k_gemm2<<<dim3(VOCAB / JB, BATCH / BT), 256, SMEM2_BYTES>>>(L, W, out);
    k_final<<<4000, 256>>>(L, out);
}

// round 8
// speedup vs baseline: 2.0524x; 1.0627x over previous
#include <cuda_runtime.h>

#define BATCH 256
#define VOCAB 128000
#define RANK  64
#define ALPHA 0.4f
#define EPSF  1.1920928955078125e-07f   // np.finfo(float32).eps

#define KC 320                  // k-chunk per gemm1 block
#define NBLK1 (VOCAB / KC)      // 400 gemm1 blocks

// ---------------- scratch (no allocations allowed) ----------------
__device__ float        g_Tpart[NBLK1 * BATCH * RANK];  // per-block partial T (26 MB)
__device__ float        g_T[BATCH * RANK];              // reduced T = L @ W
__device__ unsigned int g_maxL;                         // float bits of max|L|
__device__ unsigned int g_maxLp;                        // float bits of max|Lp_raw|

// ---------------- f32x2 / shared-memory PTX helpers ----------------
typedef unsigned long long u64;

__device__ __forceinline__ unsigned smem_u32(const void* p) {
    unsigned a;
    asm("{ .reg .u64 t; cvta.to.shared.u64 t, %1; cvt.u32.u64 %0, t; }"
        : "=r"(a) : "l"(p));
    return a;
}
__device__ __forceinline__ u64 lds_b64(unsigned a) {
    u64 v; asm volatile("ld.shared.b64 %0, [%1];" : "=l"(v) : "r"(a)); return v;
}
__device__ __forceinline__ float lds_b32(unsigned a) {
    float v; asm volatile("ld.shared.b32 %0, [%1];" : "=f"(v) : "r"(a)); return v;
}
__device__ __forceinline__ void sts_b32(unsigned a, float v) {
    asm volatile("st.shared.b32 [%0], %1;" :: "r"(a), "f"(v));
}
__device__ __forceinline__ void sts_b64(unsigned a, u64 v) {
    asm volatile("st.shared.b64 [%0], %1;" :: "r"(a), "l"(v));
}
__device__ __forceinline__ u64 fma2(u64 a, u64 b, u64 c) {
    u64 d; asm("fma.rn.f32x2 %0, %1, %2, %3;" : "=l"(d) : "l"(a), "l"(b), "l"(c));
    return d;
}
__device__ __forceinline__ u64 pack2(float x, float y) {
    u64 v; asm("mov.b64 %0, {%1,%2};" : "=l"(v) : "f"(x), "f"(y)); return v;
}
__device__ __forceinline__ void unpack2(u64 v, float& x, float& y) {
    asm("mov.b64 {%0,%1}, %2;" : "=f"(x), "=f"(y) : "l"(v));
}

// ---------------- K0: init maxima ----------------
__global__ void k_init() {
    if (threadIdx.x == 0) { g_maxL = 0u; g_maxLp = 0u; }
}

// ---------------- K1: partial T = L@W (rank-paired FFMA2, fused max|L|) ----------------
// grid = NBLK1, 256 threads. Thread tile: 8 batch x 8 rank (4 native rank-pairs).
// rank map: r = tx*2 + jp*16 (+0/1 in pair)
#define KB 32
#define LS1 33                  // Ls[b][kk] stride (scalar ops, conflict-free)
#define WS1 66                  // Ws[kk][r] stride (even -> b64-aligned pairs)
#define G1_SMEM ((BATCH * LS1 + KB * WS1) * 4)   // 33792 + 8448 B = 42240 B

__global__ __launch_bounds__(256, 2) void k_gemm1(const float* __restrict__ L,
                                                  const float* __restrict__ W) {
    extern __shared__ float sm1[];
    float* Ls = sm1;                      // [256][33]
    float* Ws = sm1 + BATCH * LS1;        // [32][66]
    __shared__ float wred[8];

    const unsigned ls_base = smem_u32(Ls);
    const unsigned ws_base = smem_u32(Ws);

    const int tid = threadIdx.x;
    const int tx  = tid & 7;    // rank-pair lane
    const int ty  = tid >> 3;   // batch group (8 rows)
    const int k0blk = blockIdx.x * KC;

    u64 acc[8][4];
#pragma unroll
    for (int i = 0; i < 8; i++)
#pragma unroll
        for (int jp = 0; jp < 4; jp++) acc[i][jp] = 0ull;

    float maxl = 0.0f;

    for (int kt = 0; kt < KC; kt += KB) {
        const int k0 = k0blk + kt;
        __syncthreads();
        // L chunk [256 b][32 k] -> Ls[b][kk] (scalar stores, conflict-free); fused abs-max
#pragma unroll
        for (int it = 0; it < 8; it++) {
            int idx = tid + it * 256;          // float4 index, 2048 total
            int b   = idx >> 3;
            int kq  = idx & 7;
            float4 v = *(const float4*)(L + (size_t)b * VOCAB + k0 + kq * 4);
            maxl = fmaxf(maxl, fmaxf(fmaxf(fabsf(v.x), fabsf(v.y)),
                                     fmaxf(fabsf(v.z), fabsf(v.w))));
            unsigned a = ls_base + (b * LS1 + kq * 4) * 4;
            sts_b32(a +  0, v.x);
            sts_b32(a +  4, v.y);
            sts_b32(a +  8, v.z);
            sts_b32(a + 12, v.w);
        }
        // W chunk [32 k][64 r] -> Ws[kk][r] (b64 stores)
#pragma unroll
        for (int it = 0; it < 2; it++) {
            int idx = tid + it * 256;          // float4 index, 512 total
            int kk  = idx >> 4;
            int rq  = idx & 15;
            float4 v = *(const float4*)(W + (size_t)(k0 + kk) * RANK + rq * 4);
            unsigned a = ws_base + (kk * WS1 + rq * 4) * 4;
            sts_b64(a + 0, pack2(v.x, v.y));
            sts_b64(a + 8, pack2(v.z, v.w));
        }
        __syncthreads();

#pragma unroll
        for (int kk = 0; kk < KB; kk++) {
            // native W rank-pairs: r = tx*2 + jp*16
            const unsigned wa = ws_base + (kk * WS1 + tx * 2) * 4;
            u64 wp[4];
#pragma unroll
            for (int jp = 0; jp < 4; jp++) wp[jp] = lds_b64(wa + jp * 64);
            // L scalars, register-duplicated
            const unsigned la = ls_base + (ty * 8 * LS1 + kk) * 4;
#pragma unroll
            for (int i = 0; i < 8; i++) {
                float lv = lds_b32(la + i * LS1 * 4);
                u64 lp = pack2(lv, lv);
#pragma unroll
                for (int jp = 0; jp < 4; jp++)
                    acc[i][jp] = fma2(lp, wp[jp], acc[i][jp]);
            }
        }
    }

    // write per-block partial tile (no atomics): g_Tpart[blk][b][r]
    {
        float* dst = g_Tpart + (size_t)blockIdx.x * (BATCH * RANK);
#pragma unroll
        for (int i = 0; i < 8; i++) {
            int b = ty * 8 + i;
#pragma unroll
            for (int jp = 0; jp < 4; jp++)
                *(u64*)(dst + b * RANK + tx * 2 + jp * 16) = acc[i][jp];
        }
    }

    // block-reduce max|L|
#pragma unroll
    for (int off = 16; off > 0; off >>= 1)
        maxl = fmaxf(maxl, __shfl_xor_sync(0xffffffffu, maxl, off));
    __syncthreads();
    if ((tid & 31) == 0) wred[tid >> 5] = maxl;
    __syncthreads();
    if (tid == 0) {
        float m = wred[0];
#pragma unroll
        for (int k = 1; k < 8; k++) m = fmaxf(m, wred[k]);
        atomicMax(&g_maxL, __float_as_uint(m));
    }
}

// ---------------- K1b: reduce partials -> g_T ----------------
__global__ void k_red() {
    int i = blockIdx.x * blockDim.x + threadIdx.x;   // 16384 threads
    float s0 = 0.f, s1 = 0.f, s2 = 0.f, s3 = 0.f;
#pragma unroll 4
    for (int p = 0; p < NBLK1; p += 4) {
        s0 += g_Tpart[(size_t)(p + 0) * (BATCH * RANK) + i];
        s1 += g_Tpart[(size_t)(p + 1) * (BATCH * RANK) + i];
        s2 += g_Tpart[(size_t)(p + 2) * (BATCH * RANK) + i];
        s3 += g_Tpart[(size_t)(p + 3) * (BATCH * RANK) + i];
    }
    g_T[i] = (s0 + s1) + (s2 + s3);
}

// ---------------- K2: Lp = T@W.T - L (batch-paired FFMA2) ----------------
// grid = (VOCAB/128, BATCH/128), 256 threads. Tile 128 b x 128 j.
// Thread: 8 b (4 native b-pairs from Tt) x 8 j (j = tx + jj*16). Scalar W -> reg dup.
#define JB 128
#define BT 128
#define TT2 130                 // Tt[r][b] stride (even -> b64 pairs aligned)
#define WS2 65                  // Ws[j][r] stride (scalar loads, conflict-free)
#define SMEM2_BYTES ((RANK * TT2 + JB * WS2) * 4)   // 33280 + 33280 B = 66560 B

__global__ __launch_bounds__(256, 2) void k_gemm2(const float* __restrict__ L,
                                                  const float* __restrict__ W,
                                                  float* __restrict__ out) {
    extern __shared__ float sm[];
    float* Tt = sm;                  // [64 r][130]
    float* Ws = sm + RANK * TT2;     // [128 j][65]

    const unsigned tt_base = smem_u32(Tt);
    const unsigned ws_base = smem_u32(Ws);

    const int tid = threadIdx.x;
    const int tx  = tid & 15;       // j lane
    const int ty  = tid >> 4;       // b group (8 rows = 4 pairs)
    const int j0  = blockIdx.x * JB;
    const int b0  = blockIdx.y * BT;

    // load T slice [128 b][64 r] transposed -> Tt[r][b]
#pragma unroll
    for (int it = 0; it < 8; it++) {
        int idx = tid + it * 256;        // float4 index, 2048 total
        int b   = idx >> 4;
        int rq  = idx & 15;
        float4 v = *(const float4*)(g_T + (size_t)(b0 + b) * RANK + rq * 4);
        unsigned a = tt_base + (rq * 4 * TT2 + b) * 4;
        sts_b32(a + 0 * TT2 * 4, v.x);
        sts_b32(a + 1 * TT2 * 4, v.y);
        sts_b32(a + 2 * TT2 * 4, v.z);
        sts_b32(a + 3 * TT2 * 4, v.w);
    }
    // load W tile [128 j][64 r] -> Ws[j][r]
#pragma unroll
    for (int it = 0; it < 8; it++) {
        int idx = tid + it * 256;        // 2048 float4
        int jj  = idx >> 4;
        int rq  = idx & 15;
        float4 v = *(const float4*)(W + (size_t)(j0 + jj) * RANK + rq * 4);
        unsigned a = ws_base + (jj * WS2 + rq * 4) * 4;
        sts_b32(a +  0, v.x);
        sts_b32(a +  4, v.y);
        sts_b32(a +  8, v.z);
        sts_b32(a + 12, v.w);
    }
    __syncthreads();

    u64 acc[4][8];                  // [b-pair][j]
#pragma unroll
    for (int ip = 0; ip < 4; ip++)
#pragma unroll
        for (int j = 0; j < 8; j++) acc[ip][j] = 0ull;

#pragma unroll 8
    for (int r = 0; r < RANK; r++) {
        // native T b-pairs: b = ty*8 + ip*2
        const unsigned ta = tt_base + (r * TT2 + ty * 8) * 4;
        u64 tp[4];
#pragma unroll
        for (int ip = 0; ip < 4; ip++) tp[ip] = lds_b64(ta + ip * 8);
        // W scalars, register-duplicated: j = tx + jj*16
        const unsigned wa = ws_base + (tx * WS2 + r) * 4;
#pragma unroll
        for (int jj = 0; jj < 8; jj++) {
            float wv = lds_b32(wa + jj * 16 * WS2 * 4);
            u64 wp = pack2(wv, wv);
#pragma unroll
            for (int ip = 0; ip < 4; ip++)
                acc[ip][jj] = fma2(tp[ip], wp, acc[ip][jj]);
        }
    }

    // epilogue: Lp = acc - L, write raw Lp, track max|Lp|
    float maxlp = 0.0f;
#pragma unroll
    for (int ip = 0; ip < 4; ip++) {
        const size_t bA = (size_t)(b0 + ty * 8 + ip * 2);
        const size_t bB = bA + 1;
#pragma unroll
        for (int jj = 0; jj < 8; jj++) {
            float lo, hi;
            unpack2(acc[ip][jj], lo, hi);
            int j = j0 + tx + jj * 16;
            float oa = lo - L[bA * VOCAB + j];
            float ob = hi - L[bB * VOCAB + j];
            maxlp = fmaxf(maxlp, fmaxf(fabsf(oa), fabsf(ob)));
            out[bA * VOCAB + j] = oa;
            out[bB * VOCAB + j] = ob;
        }
    }

#pragma unroll
    for (int off = 16; off > 0; off >>= 1)
        maxlp = fmaxf(maxlp, __shfl_xor_sync(0xffffffffu, maxlp, off));
    __syncthreads();                 // smem reads done -> reuse for reduction
    if ((tid & 31) == 0) Tt[tid >> 5] = maxlp;
    __syncthreads();
    if (tid == 0) {
        float m = Tt[0];
#pragma unroll
        for (int k = 1; k < 8; k++) m = fmaxf(m, Tt[k]);
        atomicMax(&g_maxLp, __float_as_uint(m));
    }
}

// ---------------- K3: out = (1-a)*scale*Lp + a*L ----------------
__global__ void k_final(const float* __restrict__ L, float* __restrict__ out) {
    const float maxl  = __uint_as_float(g_maxL);
    const float maxlp = __uint_as_float(g_maxLp);
    const float scale = maxl / fmaxf(maxlp, EPSF);
    const float c2 = (1.0f - ALPHA) * scale;

    const int n4 = BATCH * VOCAB / 4;
    float4* o4 = (float4*)out;
    const float4* l4 = (const float4*)L;
    for (int i = blockIdx.x * blockDim.x + threadIdx.x; i < n4;
         i += gridDim.x * blockDim.x) {
        float4 o = o4[i];
        float4 l = l4[i];
        o.x = fmaf(c2, o.x, ALPHA * l.x);
        o.y = fmaf(c2, o.y, ALPHA * l.y);
        o.z = fmaf(c2, o.z, ALPHA * l.z);
        o.w = fmaf(c2, o.w, ALPHA * l.w);
        o4[i] = o;
    }
}

// ---------------- launch ----------------
extern "C" void kernel_launch(void* const* d_in, const int* in_sizes, int n_in,
                              void* d_out, int out_size) {
    const float* L = nullptr;
    const float* W = nullptr;
    for (int i = 0; i < n_in; i++) {
        if (in_sizes[i] == BATCH * VOCAB)     L = (const float*)d_in[i];
        else if (in_sizes[i] == VOCAB * RANK) W = (const float*)d_in[i];
    }
    if (!L && n_in >= 2) L = (const float*)d_in[1];
    if (!W && n_in >= 3) W = (const float*)d_in[2];
    float* out = (float*)d_out;

    cudaFuncSetAttribute(k_gemm1, cudaFuncAttributeMaxDynamicSharedMemorySize,
                         G1_SMEM);
    cudaFuncSetAttribute(k_gemm2, cudaFuncAttributeMaxDynamicSharedMemorySize,
                         SMEM2_BYTES);

    k_init<<<1, 32>>>();
    k_gemm1<<<NBLK1, 256, G1_SMEM>>>(L, W);
    k_red<<<(BATCH * RANK) / 256, 256>>>();
    k_gemm2<<<dim3(VOCAB / JB, BATCH / BT), 256, SMEM2_BYTES>>>(L, W, out);
    k_final<<<4000, 256>>>(L, out);
}